// round 15
// baseline (speedup 1.0000x reference)
#include <cuda_runtime.h>
#include <cuda_bf16.h>
#include <cuda_fp16.h>
#include <cstdint>
#include <math.h>

#define BATCH 8
#define NPIX  4096
#define CDIM  256
#define CKDIM 32
#define ROWS  (BATCH*NPIX)   // 32768
#define NPRE  320            // 32 f | 32 g | 256 h

// ---------------- scratch (allocation-free) ----------------
__device__ __align__(16) __half g_Wpre_hi[NPRE*CDIM];  // [n][k] fp16 hi
__device__ __align__(16) __half g_Wpre_lo[NPRE*CDIM];
__device__ __align__(16) __half g_Wo_hi[CDIM*CDIM];    // [n][k]
__device__ __align__(16) __half g_Wo_lo[CDIM*CDIM];
__device__ __align__(16) __half g_f_hi[ROWS*CKDIM];
__device__ __align__(16) __half g_f_lo[ROWS*CKDIM];
__device__ __align__(16) __half g_g  [ROWS*CKDIM];     // single fp16
__device__ __align__(16) __half g_hV [ROWS*CDIM];      // V: [row][c] fp16
__device__ __align__(16) __half g_o  [ROWS*CDIM];      // single fp16

// ---------------- PTX helpers ----------------
__device__ __forceinline__ uint32_t smem_u32(const void* p) {
    uint32_t a;
    asm("{ .reg .u64 t; cvta.to.shared.u64 t, %1; cvt.u32.u64 %0, t; }" : "=r"(a) : "l"(p));
    return a;
}
#define CP_ASYNC16(dst, src) \
    asm volatile("cp.async.cg.shared.global [%0], [%1], 16;" :: "r"(dst), "l"(src))
#define CP_COMMIT() asm volatile("cp.async.commit_group;" ::: "memory")
#define CP_WAIT(n)  asm volatile("cp.async.wait_group %0;" :: "n"(n) : "memory")

__device__ __forceinline__ void ldm_x4(uint32_t r[4], uint32_t addr) {
    asm volatile("ldmatrix.sync.aligned.m8n8.x4.shared.b16 {%0,%1,%2,%3}, [%4];"
                 : "=r"(r[0]), "=r"(r[1]), "=r"(r[2]), "=r"(r[3]) : "r"(addr));
}
__device__ __forceinline__ void ldm_x4_trans(uint32_t r[4], uint32_t addr) {
    asm volatile("ldmatrix.sync.aligned.m8n8.x4.trans.shared.b16 {%0,%1,%2,%3}, [%4];"
                 : "=r"(r[0]), "=r"(r[1]), "=r"(r[2]), "=r"(r[3]) : "r"(addr));
}
__device__ __forceinline__ void mma_f16(float c[4], const uint32_t a[4], const uint32_t* b) {
    asm volatile("mma.sync.aligned.m16n8k16.row.col.f32.f16.f16.f32 "
                 "{%0,%1,%2,%3}, {%4,%5,%6,%7}, {%8,%9}, {%0,%1,%2,%3};"
                 : "+f"(c[0]), "+f"(c[1]), "+f"(c[2]), "+f"(c[3])
                 : "r"(a[0]), "r"(a[1]), "r"(a[2]), "r"(a[3]), "r"(b[0]), "r"(b[1]));
}
__device__ __forceinline__ uint32_t pack_f16(float lo, float hi) {
    uint32_t d;
    asm("cvt.rn.f16x2.f32 %0, %1, %2;" : "=r"(d) : "f"(hi), "f"(lo));
    return d;
}
__device__ __forceinline__ void split_f16(float v, __half& h, __half& l) {
    h = __float2half_rn(v);
    l = __float2half_rn(v - __half2float(h));
}
__device__ __forceinline__ uint32_t pack_h2(__half a, __half b) {
    __half2 t(a, b);
    return *reinterpret_cast<uint32_t*>(&t);
}

// ---------------------------------------------------------------------------
// Kernel 0: setup — split weights to fp16 hi/lo
// ---------------------------------------------------------------------------
#define WPREN  (NPRE*CDIM)         // 81920
#define WON    (CDIM*CDIM)         // 65536
__global__ __launch_bounds__(256) void setup_k(
        const float* __restrict__ Wf, const float* __restrict__ Wg,
        const float* __restrict__ Wh, const float* __restrict__ Wo) {
    int id = blockIdx.x*256 + threadIdx.x;
    if (id < WPREN) {
        int n = id >> 8, k = id & 255;
        float v;
        if      (n < 32) v = Wf[k*CKDIM + n];
        else if (n < 64) v = Wg[k*CKDIM + (n-32)];
        else             v = Wh[k*CDIM + (n-64)];
        __half h, l; split_f16(v, h, l);
        g_Wpre_hi[id] = h; g_Wpre_lo[id] = l;
    } else if (id < WPREN + WON) {
        int i = id - WPREN;
        int n = i >> 8, k = i & 255;
        __half h, l; split_f16(Wo[k*CDIM + n], h, l);
        g_Wo_hi[i] = h; g_Wo_lo[i] = l;
    }
}

// ---------------------------------------------------------------------------
// Kernel 1: pre-projection GEMM.  CTA = 64 rows x 160 cols, 256 thr, 2 CTA/SM.
// ---------------------------------------------------------------------------
#define P1_A    0
#define P1_W    5120
#define P1_WLO  17920
#define P1_BUF  30720
#define P1_SMEM (2*P1_BUF)

__device__ __forceinline__ void p1_loadW(uint32_t sb, int buf, int nbase,
                                         int kc, int tid) {
    const uint32_t bb = sb + buf*P1_BUF;
    #pragma unroll
    for (int i = 0; i < 5; i++) {      // 1280 x 16B, 5 per thread
        int c = tid + i*256;
        int hi = c < 640;
        int cc = hi ? c : c - 640;
        int r = cc >> 2, col = cc & 3;
        const __half* src = hi ? g_Wpre_hi : g_Wpre_lo;
        CP_ASYNC16(bb + (hi ? P1_W : P1_WLO) + r*80 + col*16,
                   (const char*)src + ((size_t)(nbase + r)*CDIM + kc*32 + col*8)*2);
    }
}

__global__ __launch_bounds__(256, 2) void pre_gemm(
        const float* __restrict__ x,
        const float* __restrict__ bfv, const float* __restrict__ bgv,
        const float* __restrict__ bhv) {
    extern __shared__ char smc[];
    const uint32_t sb = smem_u32(smc);
    const int tid  = threadIdx.x;
    const int lane = tid & 31;
    const int wid  = tid >> 5;
    const int wM   = wid & 3;       // 4 x 16 rows
    const int wNg  = wid >> 2;      // 0..1, 80 cols each
    const int row0  = (blockIdx.x >> 1) * 64;
    const int nbase = (blockIdx.x & 1) * 160;

    const int aRow = lane & 15;
    const int aK   = (lane >> 4) * 16;
    const int bR   = lane & 7;
    const int bHi8 = (lane >> 4) * 8;
    const int bK   = ((lane >> 3) & 1) * 16;

    const int xRow = tid >> 2;        // 0..63
    const int xC4  = tid & 3;         // 8-float group

    float acc[10][4];
    #pragma unroll
    for (int i = 0; i < 10; i++) { acc[i][0]=0.f; acc[i][1]=0.f; acc[i][2]=0.f; acc[i][3]=0.f; }

    const float* xrow = x + (size_t)(row0 + xRow)*CDIM + xC4*8;
    float4 xa = *(const float4*)(xrow + 0);
    float4 xb = *(const float4*)(xrow + 4);
    p1_loadW(sb, 0, nbase, 0, tid);
    CP_COMMIT();

    for (int kc = 0; kc < 8; kc++) {
        const int p = kc & 1;
        const uint32_t bb = sb + p*P1_BUF;

        // x regs -> single fp16 A smem
        {
            uint4 u;
            uint32_t* pu = (uint32_t*)&u;
            pu[0] = pack_f16(xa.x, xa.y);
            pu[1] = pack_f16(xa.z, xa.w);
            pu[2] = pack_f16(xb.x, xb.y);
            pu[3] = pack_f16(xb.z, xb.w);
            *(uint4*)(smc + p*P1_BUF + P1_A + xRow*80 + xC4*16) = u;
        }
        CP_WAIT(0);
        __syncthreads();

        if (kc < 7) {
            const float* xn = x + (size_t)(row0 + xRow)*CDIM + (kc+1)*32 + xC4*8;
            xa = *(const float4*)(xn + 0);
            xb = *(const float4*)(xn + 4);
            p1_loadW(sb, p ^ 1, nbase, kc + 1, tid);
            CP_COMMIT();
        }

        uint32_t af[2][4];
        #pragma unroll
        for (int ks = 0; ks < 2; ks++)
            ldm_x4(af[ks], bb + P1_A + (wM*16 + aRow)*80 + ks*32 + aK);
        #pragma unroll
        for (int pass = 0; pass < 2; pass++) {
            const uint32_t wb = bb + (pass == 1 ? P1_WLO : P1_W);
            #pragma unroll
            for (int ks = 0; ks < 2; ks++) {
                #pragma unroll
                for (int np = 0; np < 5; np++) {
                    uint32_t wf[4];
                    ldm_x4(wf, wb + (wNg*80 + np*16 + bHi8 + bR)*80 + ks*32 + bK);
                    mma_f16(acc[2*np],   af[ks], wf + 0);
                    mma_f16(acc[2*np+1], af[ks], wf + 2);
                }
            }
        }
        __syncthreads();
    }

    const int r0 = row0 + wM*16 + (lane >> 2);
    #pragma unroll
    for (int nt = 0; nt < 10; nt++) {
        int n = nbase + wNg*80 + nt*8 + (lane & 3)*2;
        #pragma unroll
        for (int h = 0; h < 2; h++) {
            int r = r0 + h*8;
            float v0 = acc[nt][2*h], v1 = acc[nt][2*h+1];
            if (n < 32) {
                v0 += bfv[n]; v1 += bfv[n+1];
                __half h0,l0,h1,l1; split_f16(v0,h0,l0); split_f16(v1,h1,l1);
                *(uint32_t*)&g_f_hi[(size_t)r*CKDIM + n] = pack_h2(h0,h1);
                *(uint32_t*)&g_f_lo[(size_t)r*CKDIM + n] = pack_h2(l0,l1);
            } else if (n < 64) {
                v0 += bgv[n-32]; v1 += bgv[n-31];
                *(uint32_t*)&g_g[(size_t)r*CKDIM + (n-32)] = pack_f16(v0, v1);
            } else {
                int c = n - 64;
                v0 += bhv[c]; v1 += bhv[c+1];
                *(uint32_t*)&g_hV[(size_t)r*CDIM + c] = pack_f16(v0, v1);
            }
        }
    }
}

// ---------------------------------------------------------------------------
// Kernel 3: output GEMM.  CTA = 64 rows x 128 cols, 256 thr, 2 CTA/SM.
// ---------------------------------------------------------------------------
#define P3_A    0
#define P3_W    5120
#define P3_WLO  15360
#define P3_BUF  25600
#define P3_SMEM (2*P3_BUF)

__device__ __forceinline__ void p3_load(uint32_t sb, int buf, int row0, int nbase,
                                        int kc, int tid) {
    const uint32_t bb = sb + buf*P3_BUF;
    {
        int r = tid >> 2, c = tid & 3;
        CP_ASYNC16(bb + P3_A + r*80 + c*16,
                   (const char*)g_o + ((size_t)(row0 + r)*CDIM + kc*32 + c*8)*2);
    }
    #pragma unroll
    for (int i = 0; i < 4; i++) {      // W: 1024 x 16B
        int chunk = tid + i*256;
        int hi = chunk < 512;
        int cc = hi ? chunk : chunk - 512;
        int r = cc >> 2, c = cc & 3;
        const __half* src = hi ? g_Wo_hi : g_Wo_lo;
        CP_ASYNC16(bb + (hi ? P3_W : P3_WLO) + r*80 + c*16,
                   (const char*)src + ((size_t)(nbase + r)*CDIM + kc*32 + c*8)*2);
    }
}

__global__ __launch_bounds__(256, 2) void out_gemm(
        const float* __restrict__ bov, const float* __restrict__ gammav,
        const float* __restrict__ xres, float* __restrict__ outp) {
    extern __shared__ char smc[];
    const uint32_t sb = smem_u32(smc);
    const int tid  = threadIdx.x;
    const int lane = tid & 31;
    const int wid  = tid >> 5;
    const int wM   = wid & 3;
    const int wNg  = wid >> 2;      // 0..1, 64 cols each
    const int row0  = (blockIdx.x >> 1) * 64;
    const int nbase = (blockIdx.x & 1) * 128;

    const int aRow = lane & 15;
    const int aK   = (lane >> 4) * 16;
    const int bR   = lane & 7;
    const int bHi8 = (lane >> 4) * 8;
    const int bK   = ((lane >> 3) & 1) * 16;

    float acc[8][4];
    #pragma unroll
    for (int i = 0; i < 8; i++) { acc[i][0]=0.f; acc[i][1]=0.f; acc[i][2]=0.f; acc[i][3]=0.f; }

    p3_load(sb, 0, row0, nbase, 0, tid);
    CP_COMMIT();

    for (int kc = 0; kc < 8; kc++) {
        CP_WAIT(0);
        __syncthreads();
        if (kc < 7) { p3_load(sb, (kc+1)&1, row0, nbase, kc+1, tid); CP_COMMIT(); }

        const uint32_t bb = sb + (kc&1)*P3_BUF;
        uint32_t af[2][4];
        #pragma unroll
        for (int ks = 0; ks < 2; ks++)
            ldm_x4(af[ks], bb + P3_A + (wM*16 + aRow)*80 + ks*32 + aK);
        #pragma unroll
        for (int pass = 0; pass < 2; pass++) {
            const uint32_t wb = bb + (pass == 1 ? P3_WLO : P3_W);
            #pragma unroll
            for (int ks = 0; ks < 2; ks++) {
                #pragma unroll
                for (int np = 0; np < 4; np++) {
                    uint32_t wf[4];
                    ldm_x4(wf, wb + (wNg*64 + np*16 + bHi8 + bR)*80 + ks*32 + bK);
                    mma_f16(acc[2*np],   af[ks], wf + 0);
                    mma_f16(acc[2*np+1], af[ks], wf + 2);
                }
            }
        }
        __syncthreads();
    }

    const float gam = gammav[0];
    const int r0 = row0 + wM*16 + (lane >> 2);
    #pragma unroll
    for (int nt = 0; nt < 8; nt++) {
        int n = nbase + wNg*64 + nt*8 + (lane & 3)*2;
        #pragma unroll
        for (int h = 0; h < 2; h++) {
            int r = r0 + h*8;
            float2 xr = *(const float2*)(xres + (size_t)r*CDIM + n);
            float2 o;
            o.x = gam*(acc[nt][2*h]   + bov[n])   + xr.x;
            o.y = gam*(acc[nt][2*h+1] + bov[n+1]) + xr.y;
            *(float2*)(outp + (size_t)r*CDIM + n) = o;
        }
    }
}

// ---------------------------------------------------------------------------
// Kernel 2: HMMA flash attention.
// S mapping: pair = wid>>1 (16 q-rows), half = wid&1 (32 keys).
// PV mapping: qh = wid&1 (32 q-rows), cq = wid>>1 (64 channels)  -> M=32/warp,
//   V smem reads halved.  Per-row scale/l glued via smem arrays.
// ---------------------------------------------------------------------------
#define OFF_G   0                     // 5120 (single fp16)
#define OFF_F   5120                  // 2 bufs x (hi 5120 + lo 5120)
#define OFF_V   (OFF_F + 2*10240)     // 2 bufs x 64*528 = 67584
#define OFF_P   (OFF_V + 2*33792)     // 4 pairs x 16 rows x 144B = 9216
#define OFF_MAX (OFF_P + 9216)        // 1024
#define OFF_SUM (OFF_MAX + 1024)      // 1024
#define OFF_SCL (OFF_SUM + 1024)      // 64 floats = 256
#define OFF_LFN (OFF_SCL + 256)       // 64 floats = 256
#define SMEM_ATT (OFF_LFN + 256)      // 104960 B

__device__ __forceinline__ void prefetch_F(uint32_t sb, int buf, int b, int kt, int tid) {
    const size_t kbase = (size_t)b*NPIX + (size_t)kt*64;
    int fr = tid >> 2, fc = tid & 3;
    uint32_t fd = sb + OFF_F + buf*10240 + fr*80 + fc*16;
    CP_ASYNC16(fd,        (const char*)g_f_hi + ((kbase + fr)*CKDIM + fc*8)*2);
    CP_ASYNC16(fd + 5120, (const char*)g_f_lo + ((kbase + fr)*CKDIM + fc*8)*2);
}
__device__ __forceinline__ void prefetch_V(uint32_t sb, int buf, int b, int kt, int tid) {
    const size_t kbase = (size_t)b*NPIX + (size_t)kt*64;
    #pragma unroll
    for (int i = 0; i < 8; i++) {
        int chunk = tid + i*256;
        int vr = chunk >> 5, vc = chunk & 31;
        uint32_t vd = sb + OFF_V + buf*33792 + vr*528 + vc*16;
        CP_ASYNC16(vd, (const char*)g_hV + ((kbase + vr)*CDIM + vc*8)*2);
    }
}

__global__ __launch_bounds__(256, 2) void attn_hmma() {
    extern __shared__ char smc[];
    const uint32_t sb = smem_u32(smc);
    const int tid  = threadIdx.x;
    const int lane = tid & 31;
    const int wid  = tid >> 5;
    const int pair = wid >> 1;     // S: q-rows pair*16
    const int half = wid & 1;      // S: keys half*32
    const int qh   = wid & 1;      // PV: q-rows qh*32
    const int cq   = wid >> 1;     // PV: channels cq*64
    const int b    = blockIdx.x >> 6;
    const int qt   = blockIdx.x & 63;
    const size_t qbase = (size_t)b*NPIX + qt*64;

    float* sMax = (float*)(smc + OFF_MAX);   // [pair][half][2][16]
    float* sSum = (float*)(smc + OFF_SUM);
    float* sScl = (float*)(smc + OFF_SCL);   // [64] per-row scale this tile
    float* sLfn = (float*)(smc + OFF_LFN);   // [64] final l

    const int aRow = lane & 15;
    const int aK   = (lane >> 4) * 16;
    const int bR   = lane & 7;
    const int bHi8 = (lane >> 4) * 8;
    const int bK   = ((lane >> 3) & 1) * 16;
    const int tR   = lane & 15;
    const int tC   = (lane >> 4) * 16;
    const int rq   = lane >> 2;

    const uint32_t pTile = sb + OFF_P + pair*2304;         // S-side tile
    const uint32_t pT0   = sb + OFF_P + (qh*2)*2304;       // PV A rows 0-15
    const uint32_t pT1   = sb + OFF_P + (qh*2 + 1)*2304;   // PV A rows 16-31
    float* myMax  = sMax + (pair*2 + half)*32;
    float* sibMax = sMax + (pair*2 + (half^1))*32;
    float* mySum  = sSum + (pair*2 + half)*32;
    float* sibSum = sSum + (pair*2 + (half^1))*32;

    // ---- prologue: stage G + F0 + V0
    {
        int gr = tid >> 2, gc = tid & 3;
        CP_ASYNC16(sb + OFF_G + gr*80 + gc*16,
                   (const char*)g_g + ((qbase + gr)*CKDIM + gc*8)*2);
        prefetch_F(sb, 0, b, 0, tid);
        prefetch_V(sb, 0, b, 0, tid);
        CP_COMMIT();
    }
    CP_WAIT(0);
    __syncthreads();

    uint32_t gfr[2][4];
    #pragma unroll
    for (int ks = 0; ks < 2; ks++)
        ldm_x4(gfr[ks], sb + OFF_G + (pair*16 + aRow)*80 + ks*32 + aK);

    float accO[16][4];   // [mt*8 + n8][4] : mt 0/1 -> rows qh*32 + mt*16
    #pragma unroll
    for (int i = 0; i < 16; i++) { accO[i][0]=0.f; accO[i][1]=0.f; accO[i][2]=0.f; accO[i][3]=0.f; }
    float mA = -1e30f, mB = -1e30f, lA = 0.f, lB = 0.f;
    float sc[4][4];
    float tmaxA, tmaxB;

    // ---- S(0): G x (Fhi + Flo), 2 passes
    {
        #pragma unroll
        for (int i = 0; i < 4; i++) { sc[i][0]=0.f; sc[i][1]=0.f; sc[i][2]=0.f; sc[i][3]=0.f; }
        const uint32_t fbase = sb + OFF_F;
        #pragma unroll
        for (int pass = 0; pass < 2; pass++) {
            const uint32_t fb = fbase + pass*5120;
            #pragma unroll
            for (int ks = 0; ks < 2; ks++) {
                #pragma unroll
                for (int np = 0; np < 2; np++) {
                    uint32_t fr[4];
                    ldm_x4(fr, fb + (half*32 + np*16 + bHi8 + bR)*80 + ks*32 + bK);
                    mma_f16(sc[2*np],   gfr[ks], fr + 0);
                    mma_f16(sc[2*np+1], gfr[ks], fr + 2);
                }
            }
        }
        tmaxA = -1e30f; tmaxB = -1e30f;
        #pragma unroll
        for (int nt = 0; nt < 4; nt++) {
            tmaxA = fmaxf(tmaxA, fmaxf(sc[nt][0], sc[nt][1]));
            tmaxB = fmaxf(tmaxB, fmaxf(sc[nt][2], sc[nt][3]));
        }
        tmaxA = fmaxf(tmaxA, __shfl_xor_sync(0xffffffffu, tmaxA, 1));
        tmaxA = fmaxf(tmaxA, __shfl_xor_sync(0xffffffffu, tmaxA, 2));
        tmaxB = fmaxf(tmaxB, __shfl_xor_sync(0xffffffffu, tmaxB, 1));
        tmaxB = fmaxf(tmaxB, __shfl_xor_sync(0xffffffffu, tmaxB, 2));
        if ((lane & 3) == 0) { myMax[rq] = tmaxA; myMax[16 + rq] = tmaxB; }
    }
    prefetch_F(sb, 1, b, 1, tid);
    CP_COMMIT();
    __syncthreads();   // maxes(0) visible

    for (int kt = 0; kt < 64; kt++) {
        const int bf = kt & 1;

        // ---- step1 (S mapping): scales, exp, P write, sums
        float mnA = fmaxf(mA, fmaxf(tmaxA, sibMax[rq]));
        float mnB = fmaxf(mB, fmaxf(tmaxB, sibMax[16 + rq]));
        float scA = __expf(mA - mnA), scB = __expf(mB - mnB);
        if (half == 0 && (lane & 3) == 0) {
            sScl[pair*16 + rq]     = scA;
            sScl[pair*16 + rq + 8] = scB;
        }
        float sumA = 0.f, sumB = 0.f;
        #pragma unroll
        for (int nt = 0; nt < 4; nt++) {
            float p0 = __expf(sc[nt][0] - mnA);
            float p1 = __expf(sc[nt][1] - mnA);
            float p2 = __expf(sc[nt][2] - mnB);
            float p3 = __expf(sc[nt][3] - mnB);
            sumA += p0 + p1; sumB += p2 + p3;
            uint32_t cOff = (half*32 + nt*8 + (lane & 3)*2)*2;
            *(uint32_t*)(smc + (pTile - sb) + rq*144 + cOff)       = pack_f16(p0, p1);
            *(uint32_t*)(smc + (pTile - sb) + (rq + 8)*144 + cOff) = pack_f16(p2, p3);
        }
        sumA += __shfl_xor_sync(0xffffffffu, sumA, 1);
        sumA += __shfl_xor_sync(0xffffffffu, sumA, 2);
        sumB += __shfl_xor_sync(0xffffffffu, sumB, 1);
        sumB += __shfl_xor_sync(0xffffffffu, sumB, 2);
        if ((lane & 3) == 0) { mySum[rq] = sumA; mySum[16 + rq] = sumB; }

        // ---- B1: V(kt), F(kt+1) arrived; P/sums/scales visible
        CP_WAIT(0);
        __syncthreads();

        // ---- prefetch next tile (full PV+S window)
        if (kt < 63) {
            prefetch_V(sb, bf ^ 1, b, kt + 1, tid); CP_COMMIT();
            if (kt < 62) { prefetch_F(sb, bf, b, kt + 2, tid); CP_COMMIT(); }
        }

        // ---- stats merge (S mapping)
        lA = lA*scA + sumA + sibSum[rq];
        lB = lB*scB + sumB + sibSum[16 + rq];
        mA = mnA;  mB = mnB;

        // ---- PV (PV mapping): per-row scales, conditional rescale, MMAs
        {
            float s0 = sScl[qh*32 + rq];
            float s1 = sScl[qh*32 + rq + 8];
            float s2 = sScl[qh*32 + rq + 16];
            float s3 = sScl[qh*32 + rq + 24];
            bool noscale = __all_sync(0xffffffffu,
                (s0 == 1.0f) && (s1 == 1.0f) && (s2 == 1.0f) && (s3 == 1.0f));
            if (!noscale) {
                #pragma unroll
                for (int n8 = 0; n8 < 8; n8++) {
                    accO[n8][0] *= s0; accO[n8][1] *= s0;
                    accO[n8][2] *= s1; accO[n8][3] *= s1;
                    accO[8+n8][0] *= s2; accO[8+n8][1] *= s2;
                    accO[8+n8][2] *= s3; accO[8+n8][3] *= s3;
                }
            }
            const uint32_t vbase = sb + OFF_V + bf*33792 + cq*128;
            #pragma unroll
            for (int ks = 0; ks < 4; ks++) {
                uint32_t pa0[4], pa1[4];
                ldm_x4(pa0, pT0 + aRow*144 + ks*32 + aK);
                ldm_x4(pa1, pT1 + aRow*144 + ks*32 + aK);
                #pragma unroll
                for (int np = 0; np < 4; np++) {
                    uint32_t vr[4];
                    ldm_x4_trans(vr, vbase + (ks*16 + tR)*528 + np*32 + tC);
                    mma_f16(accO[2*np],     pa0, vr + 0);
                    mma_f16(accO[2*np+1],   pa0, vr + 2);
                    mma_f16(accO[8+2*np],   pa1, vr + 0);
                    mma_f16(accO[8+2*np+1], pa1, vr + 2);
                }
            }
        }

        // ---- S(kt+1) (S mapping)
        if (kt < 63) {
            #pragma unroll
            for (int i = 0; i < 4; i++) { sc[i][0]=0.f; sc[i][1]=0.f; sc[i][2]=0.f; sc[i][3]=0.f; }
            const uint32_t fbase = sb + OFF_F + (bf^1)*10240;
            #pragma unroll
            for (int pass = 0; pass < 2; pass++) {
                const uint32_t fb = fbase + pass*5120;
                #pragma unroll
                for (int ks = 0; ks < 2; ks++) {
                    #pragma unroll
                    for (int np = 0; np < 2; np++) {
                        uint32_t fr[4];
                        ldm_x4(fr, fb + (half*32 + np*16 + bHi8 + bR)*80 + ks*32 + bK);
                        mma_f16(sc[2*np],   gfr[ks], fr + 0);
                        mma_f16(sc[2*np+1], gfr[ks], fr + 2);
                    }
                }
            }
            tmaxA = -1e30f; tmaxB = -1e30f;
            #pragma unroll
            for (int nt = 0; nt < 4; nt++) {
                tmaxA = fmaxf(tmaxA, fmaxf(sc[nt][0], sc[nt][1]));
                tmaxB = fmaxf(tmaxB, fmaxf(sc[nt][2], sc[nt][3]));
            }
            tmaxA = fmaxf(tmaxA, __shfl_xor_sync(0xffffffffu, tmaxA, 1));
            tmaxA = fmaxf(tmaxA, __shfl_xor_sync(0xffffffffu, tmaxA, 2));
            tmaxB = fmaxf(tmaxB, __shfl_xor_sync(0xffffffffu, tmaxB, 1));
            tmaxB = fmaxf(tmaxB, __shfl_xor_sync(0xffffffffu, tmaxB, 2));
            if ((lane & 3) == 0) { myMax[rq] = tmaxA; myMax[16 + rq] = tmaxB; }
        }

        __syncthreads();   // B2: max(kt+1) visible; P tile consumed
    }

    // ---- export final l (S mapping) -> epilogue (PV mapping)
    if (half == 0 && (lane & 3) == 0) {
        sLfn[pair*16 + rq]     = lA;
        sLfn[pair*16 + rq + 8] = lB;
    }
    __syncthreads();
    const float inv0 = 1.0f / sLfn[qh*32 + rq];
    const float inv1 = 1.0f / sLfn[qh*32 + rq + 8];
    const float inv2 = 1.0f / sLfn[qh*32 + rq + 16];
    const float inv3 = 1.0f / sLfn[qh*32 + rq + 24];

    const size_t r00 = qbase + qh*32 + rq;
    #pragma unroll
    for (int n8 = 0; n8 < 8; n8++) {
        int c = cq*64 + n8*8 + (lane & 3)*2;
        *(uint32_t*)&g_o[(r00     )*CDIM + c] = pack_f16(accO[n8][0]*inv0,   accO[n8][1]*inv0);
        *(uint32_t*)&g_o[(r00 +  8)*CDIM + c] = pack_f16(accO[n8][2]*inv1,   accO[n8][3]*inv1);
        *(uint32_t*)&g_o[(r00 + 16)*CDIM + c] = pack_f16(accO[8+n8][0]*inv2, accO[8+n8][1]*inv2);
        *(uint32_t*)&g_o[(r00 + 24)*CDIM + c] = pack_f16(accO[8+n8][2]*inv3, accO[8+n8][3]*inv3);
    }
}

// ---------------------------------------------------------------------------
extern "C" void kernel_launch(void* const* d_in, const int* in_sizes, int n_in,
                              void* d_out, int out_size) {
    const float* x     = (const float*)d_in[0];
    const float* Wf    = (const float*)d_in[1];
    const float* bf    = (const float*)d_in[2];
    const float* Wg    = (const float*)d_in[3];
    const float* bg    = (const float*)d_in[4];
    const float* Wh    = (const float*)d_in[5];
    const float* bh    = (const float*)d_in[6];
    const float* Wo    = (const float*)d_in[7];
    const float* bo    = (const float*)d_in[8];
    const float* gamma = (const float*)d_in[9];
    float*       out   = (float*)d_out;

    cudaFuncSetAttribute(pre_gemm,  cudaFuncAttributeMaxDynamicSharedMemorySize, P1_SMEM);
    cudaFuncSetAttribute(out_gemm,  cudaFuncAttributeMaxDynamicSharedMemorySize, P3_SMEM);
    cudaFuncSetAttribute(attn_hmma, cudaFuncAttributeMaxDynamicSharedMemorySize, SMEM_ATT);

    const int setup_blocks = (WPREN + WON + 255) / 256;   // 576
    setup_k<<<setup_blocks, 256>>>(Wf, Wg, Wh, Wo);
    pre_gemm<<<ROWS/64*2, 256, P1_SMEM>>>(x, bf, bg, bh);
    attn_hmma<<<512, 256, SMEM_ATT>>>();
    out_gemm<<<ROWS/64*2, 256, P3_SMEM>>>(bo, gamma, x, out);
}

// round 16
// speedup vs baseline: 1.1340x; 1.1340x over previous
#include <cuda_runtime.h>
#include <cuda_bf16.h>
#include <cuda_fp16.h>
#include <cstdint>
#include <math.h>

#define BATCH 8
#define NPIX  4096
#define CDIM  256
#define CKDIM 32
#define ROWS  (BATCH*NPIX)   // 32768
#define NPRE  320            // 32 f | 32 g | 256 h

// ---------------- scratch (allocation-free) ----------------
__device__ __align__(16) __half g_Wpre_hi[NPRE*CDIM];  // [n][k] fp16 hi
__device__ __align__(16) __half g_Wpre_lo[NPRE*CDIM];
__device__ __align__(16) __half g_Wo_hi[CDIM*CDIM];    // [n][k]
__device__ __align__(16) __half g_Wo_lo[CDIM*CDIM];
__device__ __align__(16) __half g_f_hi[ROWS*CKDIM];
__device__ __align__(16) __half g_f_lo[ROWS*CKDIM];
__device__ __align__(16) __half g_g  [ROWS*CKDIM];     // single fp16
__device__ __align__(16) __half g_hV [ROWS*CDIM];      // V: [row][c] fp16
__device__ __align__(16) __half g_o  [ROWS*CDIM];      // single fp16

// ---------------- PTX helpers ----------------
__device__ __forceinline__ uint32_t smem_u32(const void* p) {
    uint32_t a;
    asm("{ .reg .u64 t; cvta.to.shared.u64 t, %1; cvt.u32.u64 %0, t; }" : "=r"(a) : "l"(p));
    return a;
}
#define CP_ASYNC16(dst, src) \
    asm volatile("cp.async.cg.shared.global [%0], [%1], 16;" :: "r"(dst), "l"(src))
#define CP_COMMIT() asm volatile("cp.async.commit_group;" ::: "memory")
#define CP_WAIT(n)  asm volatile("cp.async.wait_group %0;" :: "n"(n) : "memory")
#define BAR_PAIR(id) asm volatile("bar.sync %0, 64;" :: "r"(id) : "memory")

__device__ __forceinline__ void ldm_x4(uint32_t r[4], uint32_t addr) {
    asm volatile("ldmatrix.sync.aligned.m8n8.x4.shared.b16 {%0,%1,%2,%3}, [%4];"
                 : "=r"(r[0]), "=r"(r[1]), "=r"(r[2]), "=r"(r[3]) : "r"(addr));
}
__device__ __forceinline__ void ldm_x4_trans(uint32_t r[4], uint32_t addr) {
    asm volatile("ldmatrix.sync.aligned.m8n8.x4.trans.shared.b16 {%0,%1,%2,%3}, [%4];"
                 : "=r"(r[0]), "=r"(r[1]), "=r"(r[2]), "=r"(r[3]) : "r"(addr));
}
__device__ __forceinline__ void mma_f16(float c[4], const uint32_t a[4], const uint32_t* b) {
    asm volatile("mma.sync.aligned.m16n8k16.row.col.f32.f16.f16.f32 "
                 "{%0,%1,%2,%3}, {%4,%5,%6,%7}, {%8,%9}, {%0,%1,%2,%3};"
                 : "+f"(c[0]), "+f"(c[1]), "+f"(c[2]), "+f"(c[3])
                 : "r"(a[0]), "r"(a[1]), "r"(a[2]), "r"(a[3]), "r"(b[0]), "r"(b[1]));
}
__device__ __forceinline__ uint32_t pack_f16(float lo, float hi) {
    uint32_t d;
    asm("cvt.rn.f16x2.f32 %0, %1, %2;" : "=r"(d) : "f"(hi), "f"(lo));
    return d;
}
__device__ __forceinline__ void split_f16(float v, __half& h, __half& l) {
    h = __float2half_rn(v);
    l = __float2half_rn(v - __half2float(h));
}
__device__ __forceinline__ uint32_t pack_h2(__half a, __half b) {
    __half2 t(a, b);
    return *reinterpret_cast<uint32_t*>(&t);
}

// ---------------------------------------------------------------------------
// Kernel 0: setup — split weights to fp16 hi/lo
// ---------------------------------------------------------------------------
#define WPREN  (NPRE*CDIM)         // 81920
#define WON    (CDIM*CDIM)         // 65536
__global__ __launch_bounds__(256) void setup_k(
        const float* __restrict__ Wf, const float* __restrict__ Wg,
        const float* __restrict__ Wh, const float* __restrict__ Wo) {
    int id = blockIdx.x*256 + threadIdx.x;
    if (id < WPREN) {
        int n = id >> 8, k = id & 255;
        float v;
        if      (n < 32) v = Wf[k*CKDIM + n];
        else if (n < 64) v = Wg[k*CKDIM + (n-32)];
        else             v = Wh[k*CDIM + (n-64)];
        __half h, l; split_f16(v, h, l);
        g_Wpre_hi[id] = h; g_Wpre_lo[id] = l;
    } else if (id < WPREN + WON) {
        int i = id - WPREN;
        int n = i >> 8, k = i & 255;
        __half h, l; split_f16(Wo[k*CDIM + n], h, l);
        g_Wo_hi[i] = h; g_Wo_lo[i] = l;
    }
}

// ---------------------------------------------------------------------------
// Kernel 1: pre-projection GEMM.  CTA = 64 rows x 160 cols, 256 thr, 2 CTA/SM.
// A: x fp32 -> regs -> single fp16 STS.  W: fp16 hi/lo cp.async.  2 MMA passes.
// ---------------------------------------------------------------------------
#define P1_A    0
#define P1_W    5120
#define P1_WLO  17920
#define P1_BUF  30720
#define P1_SMEM (2*P1_BUF)

__device__ __forceinline__ void p1_loadW(uint32_t sb, int buf, int nbase,
                                         int kc, int tid) {
    const uint32_t bb = sb + buf*P1_BUF;
    #pragma unroll
    for (int i = 0; i < 5; i++) {      // 1280 x 16B, 5 per thread
        int c = tid + i*256;
        int hi = c < 640;
        int cc = hi ? c : c - 640;
        int r = cc >> 2, col = cc & 3;
        const __half* src = hi ? g_Wpre_hi : g_Wpre_lo;
        CP_ASYNC16(bb + (hi ? P1_W : P1_WLO) + r*80 + col*16,
                   (const char*)src + ((size_t)(nbase + r)*CDIM + kc*32 + col*8)*2);
    }
}

__global__ __launch_bounds__(256, 2) void pre_gemm(
        const float* __restrict__ x,
        const float* __restrict__ bfv, const float* __restrict__ bgv,
        const float* __restrict__ bhv) {
    extern __shared__ char smc[];
    const uint32_t sb = smem_u32(smc);
    const int tid  = threadIdx.x;
    const int lane = tid & 31;
    const int wid  = tid >> 5;
    const int wM   = wid & 3;       // 4 x 16 rows
    const int wNg  = wid >> 2;      // 0..1, 80 cols each
    const int row0  = (blockIdx.x >> 1) * 64;
    const int nbase = (blockIdx.x & 1) * 160;

    const int aRow = lane & 15;
    const int aK   = (lane >> 4) * 16;
    const int bR   = lane & 7;
    const int bHi8 = (lane >> 4) * 8;
    const int bK   = ((lane >> 3) & 1) * 16;

    const int xRow = tid >> 2;        // 0..63
    const int xC4  = tid & 3;         // 8-float group

    float acc[10][4];
    #pragma unroll
    for (int i = 0; i < 10; i++) { acc[i][0]=0.f; acc[i][1]=0.f; acc[i][2]=0.f; acc[i][3]=0.f; }

    const float* xrow = x + (size_t)(row0 + xRow)*CDIM + xC4*8;
    float4 xa = *(const float4*)(xrow + 0);
    float4 xb = *(const float4*)(xrow + 4);
    p1_loadW(sb, 0, nbase, 0, tid);
    CP_COMMIT();

    for (int kc = 0; kc < 8; kc++) {
        const int p = kc & 1;
        const uint32_t bb = sb + p*P1_BUF;

        // x regs -> single fp16 A smem
        {
            uint4 u;
            uint32_t* pu = (uint32_t*)&u;
            pu[0] = pack_f16(xa.x, xa.y);
            pu[1] = pack_f16(xa.z, xa.w);
            pu[2] = pack_f16(xb.x, xb.y);
            pu[3] = pack_f16(xb.z, xb.w);
            *(uint4*)(smc + p*P1_BUF + P1_A + xRow*80 + xC4*16) = u;
        }
        CP_WAIT(0);
        __syncthreads();

        if (kc < 7) {
            const float* xn = x + (size_t)(row0 + xRow)*CDIM + (kc+1)*32 + xC4*8;
            xa = *(const float4*)(xn + 0);
            xb = *(const float4*)(xn + 4);
            p1_loadW(sb, p ^ 1, nbase, kc + 1, tid);
            CP_COMMIT();
        }

        uint32_t af[2][4];
        #pragma unroll
        for (int ks = 0; ks < 2; ks++)
            ldm_x4(af[ks], bb + P1_A + (wM*16 + aRow)*80 + ks*32 + aK);
        #pragma unroll
        for (int pass = 0; pass < 2; pass++) {
            const uint32_t wb = bb + (pass == 1 ? P1_WLO : P1_W);
            #pragma unroll
            for (int ks = 0; ks < 2; ks++) {
                #pragma unroll
                for (int np = 0; np < 5; np++) {
                    uint32_t wf[4];
                    ldm_x4(wf, wb + (wNg*80 + np*16 + bHi8 + bR)*80 + ks*32 + bK);
                    mma_f16(acc[2*np],   af[ks], wf + 0);
                    mma_f16(acc[2*np+1], af[ks], wf + 2);
                }
            }
        }
        __syncthreads();
    }

    const int r0 = row0 + wM*16 + (lane >> 2);
    #pragma unroll
    for (int nt = 0; nt < 10; nt++) {
        int n = nbase + wNg*80 + nt*8 + (lane & 3)*2;
        #pragma unroll
        for (int h = 0; h < 2; h++) {
            int r = r0 + h*8;
            float v0 = acc[nt][2*h], v1 = acc[nt][2*h+1];
            if (n < 32) {
                v0 += bfv[n]; v1 += bfv[n+1];
                __half h0,l0,h1,l1; split_f16(v0,h0,l0); split_f16(v1,h1,l1);
                *(uint32_t*)&g_f_hi[(size_t)r*CKDIM + n] = pack_h2(h0,h1);
                *(uint32_t*)&g_f_lo[(size_t)r*CKDIM + n] = pack_h2(l0,l1);
            } else if (n < 64) {
                v0 += bgv[n-32]; v1 += bgv[n-31];
                *(uint32_t*)&g_g[(size_t)r*CKDIM + (n-32)] = pack_f16(v0, v1);
            } else {
                int c = n - 64;
                v0 += bhv[c]; v1 += bhv[c+1];
                *(uint32_t*)&g_hV[(size_t)r*CDIM + c] = pack_f16(v0, v1);
            }
        }
    }
}

// ---------------------------------------------------------------------------
// Kernel 3: output GEMM.  CTA = 64 rows x 128 cols, 256 thr, 2 CTA/SM.
// ---------------------------------------------------------------------------
#define P3_A    0
#define P3_W    5120
#define P3_WLO  15360
#define P3_BUF  25600
#define P3_SMEM (2*P3_BUF)

__device__ __forceinline__ void p3_load(uint32_t sb, int buf, int row0, int nbase,
                                        int kc, int tid) {
    const uint32_t bb = sb + buf*P3_BUF;
    {
        int r = tid >> 2, c = tid & 3;
        CP_ASYNC16(bb + P3_A + r*80 + c*16,
                   (const char*)g_o + ((size_t)(row0 + r)*CDIM + kc*32 + c*8)*2);
    }
    #pragma unroll
    for (int i = 0; i < 4; i++) {      // W: 1024 x 16B
        int chunk = tid + i*256;
        int hi = chunk < 512;
        int cc = hi ? chunk : chunk - 512;
        int r = cc >> 2, c = cc & 3;
        const __half* src = hi ? g_Wo_hi : g_Wo_lo;
        CP_ASYNC16(bb + (hi ? P3_W : P3_WLO) + r*80 + c*16,
                   (const char*)src + ((size_t)(nbase + r)*CDIM + kc*32 + c*8)*2);
    }
}

__global__ __launch_bounds__(256, 2) void out_gemm(
        const float* __restrict__ bov, const float* __restrict__ gammav,
        const float* __restrict__ xres, float* __restrict__ outp) {
    extern __shared__ char smc[];
    const uint32_t sb = smem_u32(smc);
    const int tid  = threadIdx.x;
    const int lane = tid & 31;
    const int wid  = tid >> 5;
    const int wM   = wid & 3;
    const int wNg  = wid >> 2;      // 0..1, 64 cols each
    const int row0  = (blockIdx.x >> 1) * 64;
    const int nbase = (blockIdx.x & 1) * 128;

    const int aRow = lane & 15;
    const int aK   = (lane >> 4) * 16;
    const int bR   = lane & 7;
    const int bHi8 = (lane >> 4) * 8;
    const int bK   = ((lane >> 3) & 1) * 16;

    float acc[8][4];
    #pragma unroll
    for (int i = 0; i < 8; i++) { acc[i][0]=0.f; acc[i][1]=0.f; acc[i][2]=0.f; acc[i][3]=0.f; }

    p3_load(sb, 0, row0, nbase, 0, tid);
    CP_COMMIT();

    for (int kc = 0; kc < 8; kc++) {
        CP_WAIT(0);
        __syncthreads();
        if (kc < 7) { p3_load(sb, (kc+1)&1, row0, nbase, kc+1, tid); CP_COMMIT(); }

        const uint32_t bb = sb + (kc&1)*P3_BUF;
        uint32_t af[2][4];
        #pragma unroll
        for (int ks = 0; ks < 2; ks++)
            ldm_x4(af[ks], bb + P3_A + (wM*16 + aRow)*80 + ks*32 + aK);
        #pragma unroll
        for (int pass = 0; pass < 2; pass++) {
            const uint32_t wb = bb + (pass == 1 ? P3_WLO : P3_W);
            #pragma unroll
            for (int ks = 0; ks < 2; ks++) {
                #pragma unroll
                for (int np = 0; np < 4; np++) {
                    uint32_t wf[4];
                    ldm_x4(wf, wb + (wNg*64 + np*16 + bHi8 + bR)*80 + ks*32 + bK);
                    mma_f16(acc[2*np],   af[ks], wf + 0);
                    mma_f16(acc[2*np+1], af[ks], wf + 2);
                }
            }
        }
        __syncthreads();
    }

    const float gam = gammav[0];
    const int r0 = row0 + wM*16 + (lane >> 2);
    #pragma unroll
    for (int nt = 0; nt < 8; nt++) {
        int n = nbase + wNg*64 + nt*8 + (lane & 3)*2;
        #pragma unroll
        for (int h = 0; h < 2; h++) {
            int r = r0 + h*8;
            float2 xr = *(const float2*)(xres + (size_t)r*CDIM + n);
            float2 o;
            o.x = gam*(acc[nt][2*h]   + bov[n])   + xr.x;
            o.y = gam*(acc[nt][2*h+1] + bov[n+1]) + xr.y;
            *(float2*)(outp + (size_t)r*CDIM + n) = o;
        }
    }
}

// ---------------------------------------------------------------------------
// Kernel 2: HMMA flash attention (R14 mapping), pair-split, fp16 S 2-pass.
// B2 is a per-pair named barrier (64 threads) — pairs can skew.
// ---------------------------------------------------------------------------
#define OFF_G   0                     // 5120 (single fp16)
#define OFF_F   5120                  // 2 bufs x (hi 5120 + lo 5120)
#define OFF_V   (OFF_F + 2*10240)     // 2 bufs x 64*528 = 67584
#define OFF_P   (OFF_V + 2*33792)     // 4 pairs x 16 rows x 144B = 9216
#define OFF_MAX (OFF_P + 9216)        // 1024
#define OFF_SUM (OFF_MAX + 1024)      // 1024
#define SMEM_ATT (OFF_SUM + 1024)     // 104448 B

__device__ __forceinline__ void prefetch_F(uint32_t sb, int buf, int b, int kt, int tid) {
    const size_t kbase = (size_t)b*NPIX + (size_t)kt*64;
    int fr = tid >> 2, fc = tid & 3;
    uint32_t fd = sb + OFF_F + buf*10240 + fr*80 + fc*16;
    CP_ASYNC16(fd,        (const char*)g_f_hi + ((kbase + fr)*CKDIM + fc*8)*2);
    CP_ASYNC16(fd + 5120, (const char*)g_f_lo + ((kbase + fr)*CKDIM + fc*8)*2);
}
__device__ __forceinline__ void prefetch_V(uint32_t sb, int buf, int b, int kt, int tid) {
    const size_t kbase = (size_t)b*NPIX + (size_t)kt*64;
    #pragma unroll
    for (int i = 0; i < 8; i++) {
        int chunk = tid + i*256;
        int vr = chunk >> 5, vc = chunk & 31;
        uint32_t vd = sb + OFF_V + buf*33792 + vr*528 + vc*16;
        CP_ASYNC16(vd, (const char*)g_hV + ((kbase + vr)*CDIM + vc*8)*2);
    }
}

__global__ __launch_bounds__(256, 2) void attn_hmma() {
    extern __shared__ char smc[];
    const uint32_t sb = smem_u32(smc);
    const int tid  = threadIdx.x;
    const int lane = tid & 31;
    const int wid  = tid >> 5;
    const int pair = wid >> 1;     // 0..3 : q-rows pair*16
    const int half = wid & 1;      // 0..1 : keys half*32 (S), ch half*128 (PV)
    const int b    = blockIdx.x >> 6;
    const int qt   = blockIdx.x & 63;
    const size_t qbase = (size_t)b*NPIX + qt*64;

    float* sMax = (float*)(smc + OFF_MAX);   // [pair][half][2][16]
    float* sSum = (float*)(smc + OFF_SUM);

    const int aRow = lane & 15;
    const int aK   = (lane >> 4) * 16;
    const int bR   = lane & 7;
    const int bHi8 = (lane >> 4) * 8;
    const int bK   = ((lane >> 3) & 1) * 16;
    const int tR   = lane & 15;
    const int tC   = (lane >> 4) * 16;
    const int rq   = lane >> 2;

    const uint32_t pTile = sb + OFF_P + pair*2304;
    float* myMax  = sMax + (pair*2 + half)*32;
    float* sibMax = sMax + (pair*2 + (half^1))*32;
    float* mySum  = sSum + (pair*2 + half)*32;
    float* sibSum = sSum + (pair*2 + (half^1))*32;

    // ---- prologue: stage G + F0 + V0
    {
        int gr = tid >> 2, gc = tid & 3;
        CP_ASYNC16(sb + OFF_G + gr*80 + gc*16,
                   (const char*)g_g + ((qbase + gr)*CKDIM + gc*8)*2);
        prefetch_F(sb, 0, b, 0, tid);
        prefetch_V(sb, 0, b, 0, tid);
        CP_COMMIT();
    }
    CP_WAIT(0);
    __syncthreads();

    uint32_t gfr[2][4];
    #pragma unroll
    for (int ks = 0; ks < 2; ks++)
        ldm_x4(gfr[ks], sb + OFF_G + (pair*16 + aRow)*80 + ks*32 + aK);

    float accO[16][4];
    #pragma unroll
    for (int i = 0; i < 16; i++) { accO[i][0]=0.f; accO[i][1]=0.f; accO[i][2]=0.f; accO[i][3]=0.f; }
    float mA = -1e30f, mB = -1e30f, lA = 0.f, lB = 0.f;
    float sc[4][4];
    float tmaxA, tmaxB;

    // ---- S(0): G x (Fhi + Flo), 2 passes
    {
        #pragma unroll
        for (int i = 0; i < 4; i++) { sc[i][0]=0.f; sc[i][1]=0.f; sc[i][2]=0.f; sc[i][3]=0.f; }
        const uint32_t fbase = sb + OFF_F;
        #pragma unroll
        for (int pass = 0; pass < 2; pass++) {
            const uint32_t fb = fbase + pass*5120;
            #pragma unroll
            for (int ks = 0; ks < 2; ks++) {
                #pragma unroll
                for (int np = 0; np < 2; np++) {
                    uint32_t fr[4];
                    ldm_x4(fr, fb + (half*32 + np*16 + bHi8 + bR)*80 + ks*32 + bK);
                    mma_f16(sc[2*np],   gfr[ks], fr + 0);
                    mma_f16(sc[2*np+1], gfr[ks], fr + 2);
                }
            }
        }
        tmaxA = -1e30f; tmaxB = -1e30f;
        #pragma unroll
        for (int nt = 0; nt < 4; nt++) {
            tmaxA = fmaxf(tmaxA, fmaxf(sc[nt][0], sc[nt][1]));
            tmaxB = fmaxf(tmaxB, fmaxf(sc[nt][2], sc[nt][3]));
        }
        tmaxA = fmaxf(tmaxA, __shfl_xor_sync(0xffffffffu, tmaxA, 1));
        tmaxA = fmaxf(tmaxA, __shfl_xor_sync(0xffffffffu, tmaxA, 2));
        tmaxB = fmaxf(tmaxB, __shfl_xor_sync(0xffffffffu, tmaxB, 1));
        tmaxB = fmaxf(tmaxB, __shfl_xor_sync(0xffffffffu, tmaxB, 2));
        if ((lane & 3) == 0) { myMax[rq] = tmaxA; myMax[16 + rq] = tmaxB; }
    }
    prefetch_F(sb, 1, b, 1, tid);
    CP_COMMIT();
    __syncthreads();   // maxes(0) visible

    for (int kt = 0; kt < 64; kt++) {
        const int bf = kt & 1;

        // ---- step1: exp(kt) + P write + sums
        float mnA = fmaxf(mA, fmaxf(tmaxA, sibMax[rq]));
        float mnB = fmaxf(mB, fmaxf(tmaxB, sibMax[16 + rq]));
        float scA = __expf(mA - mnA), scB = __expf(mB - mnB);
        bool noscale = __all_sync(0xffffffffu, (scA == 1.0f) && (scB == 1.0f));
        float sumA = 0.f, sumB = 0.f;
        #pragma unroll
        for (int nt = 0; nt < 4; nt++) {
            float p0 = __expf(sc[nt][0] - mnA);
            float p1 = __expf(sc[nt][1] - mnA);
            float p2 = __expf(sc[nt][2] - mnB);
            float p3 = __expf(sc[nt][3] - mnB);
            sumA += p0 + p1; sumB += p2 + p3;
            uint32_t cOff = (half*32 + nt*8 + (lane & 3)*2)*2;
            *(uint32_t*)(smc + (pTile - sb) + rq*144 + cOff)       = pack_f16(p0, p1);
            *(uint32_t*)(smc + (pTile - sb) + (rq + 8)*144 + cOff) = pack_f16(p2, p3);
        }
        sumA += __shfl_xor_sync(0xffffffffu, sumA, 1);
        sumA += __shfl_xor_sync(0xffffffffu, sumA, 2);
        sumB += __shfl_xor_sync(0xffffffffu, sumB, 1);
        sumB += __shfl_xor_sync(0xffffffffu, sumB, 2);
        if ((lane & 3) == 0) { mySum[rq] = sumA; mySum[16 + rq] = sumB; }

        // ---- B1 (full CTA): V(kt), F(kt+1) arrived; P/sums visible
        CP_WAIT(0);
        __syncthreads();

        // ---- prefetch next tile (full PV+S window before next B1)
        if (kt < 63) {
            prefetch_V(sb, bf ^ 1, b, kt + 1, tid); CP_COMMIT();
            if (kt < 62) { prefetch_F(sb, bf, b, kt + 2, tid); CP_COMMIT(); }
        }

        // ---- step3: stats merge + (conditional) rescale + PV(kt)
        lA = lA*scA + sumA + sibSum[rq];
        lB = lB*scB + sumB + sibSum[16 + rq];
        mA = mnA;  mB = mnB;
        if (!noscale) {
            #pragma unroll
            for (int nt = 0; nt < 16; nt++) {
                accO[nt][0] *= scA; accO[nt][1] *= scA;
                accO[nt][2] *= scB; accO[nt][3] *= scB;
            }
        }
        uint32_t pa[4][4];
        #pragma unroll
        for (int ks = 0; ks < 4; ks++)
            ldm_x4(pa[ks], pTile + aRow*144 + ks*32 + aK);
        const uint32_t vbase = sb + OFF_V + bf*33792 + half*256;
        #pragma unroll
        for (int ks = 0; ks < 4; ks++) {
            #pragma unroll
            for (int np = 0; np < 8; np++) {
                uint32_t vr[4];
                ldm_x4_trans(vr, vbase + (ks*16 + tR)*528 + np*32 + tC);
                mma_f16(accO[2*np],   pa[ks], vr + 0);
                mma_f16(accO[2*np+1], pa[ks], vr + 2);
            }
        }

        // ---- step4: S(kt+1) + own max + max write
        if (kt < 63) {
            #pragma unroll
            for (int i = 0; i < 4; i++) { sc[i][0]=0.f; sc[i][1]=0.f; sc[i][2]=0.f; sc[i][3]=0.f; }
            const uint32_t fbase = sb + OFF_F + (bf^1)*10240;
            #pragma unroll
            for (int pass = 0; pass < 2; pass++) {
                const uint32_t fb = fbase + pass*5120;
                #pragma unroll
                for (int ks = 0; ks < 2; ks++) {
                    #pragma unroll
                    for (int np = 0; np < 2; np++) {
                        uint32_t fr[4];
                        ldm_x4(fr, fb + (half*32 + np*16 + bHi8 + bR)*80 + ks*32 + bK);
                        mma_f16(sc[2*np],   gfr[ks], fr + 0);
                        mma_f16(sc[2*np+1], gfr[ks], fr + 2);
                    }
                }
            }
            tmaxA = -1e30f; tmaxB = -1e30f;
            #pragma unroll
            for (int nt = 0; nt < 4; nt++) {
                tmaxA = fmaxf(tmaxA, fmaxf(sc[nt][0], sc[nt][1]));
                tmaxB = fmaxf(tmaxB, fmaxf(sc[nt][2], sc[nt][3]));
            }
            tmaxA = fmaxf(tmaxA, __shfl_xor_sync(0xffffffffu, tmaxA, 1));
            tmaxA = fmaxf(tmaxA, __shfl_xor_sync(0xffffffffu, tmaxA, 2));
            tmaxB = fmaxf(tmaxB, __shfl_xor_sync(0xffffffffu, tmaxB, 1));
            tmaxB = fmaxf(tmaxB, __shfl_xor_sync(0xffffffffu, tmaxB, 2));
            if ((lane & 3) == 0) { myMax[rq] = tmaxA; myMax[16 + rq] = tmaxB; }
        }

        // ---- B2 (per-pair named barrier): max(kt+1)/P-tile ordering, pair-local.
        // V-buffer overwrite safety is carried by B1 (per-warp program order +
        // full-CTA join before any next-tile prefetch writes).
        BAR_PAIR(pair + 1);
    }

    // ---- epilogue: write single fp16 o ----
    const float invA = 1.0f / lA, invB = 1.0f / lB;
    const size_t rA = qbase + pair*16 + rq;
    const size_t rB = rA + 8;
    #pragma unroll
    for (int nt = 0; nt < 16; nt++) {
        int c = half*128 + nt*8 + (lane & 3)*2;
        *(uint32_t*)&g_o[rA*CDIM + c] = pack_f16(accO[nt][0]*invA, accO[nt][1]*invA);
        *(uint32_t*)&g_o[rB*CDIM + c] = pack_f16(accO[nt][2]*invB, accO[nt][3]*invB);
    }
}

// ---------------------------------------------------------------------------
extern "C" void kernel_launch(void* const* d_in, const int* in_sizes, int n_in,
                              void* d_out, int out_size) {
    const float* x     = (const float*)d_in[0];
    const float* Wf    = (const float*)d_in[1];
    const float* bf    = (const float*)d_in[2];
    const float* Wg    = (const float*)d_in[3];
    const float* bg    = (const float*)d_in[4];
    const float* Wh    = (const float*)d_in[5];
    const float* bh    = (const float*)d_in[6];
    const float* Wo    = (const float*)d_in[7];
    const float* bo    = (const float*)d_in[8];
    const float* gamma = (const float*)d_in[9];
    float*       out   = (float*)d_out;

    cudaFuncSetAttribute(pre_gemm,  cudaFuncAttributeMaxDynamicSharedMemorySize, P1_SMEM);
    cudaFuncSetAttribute(out_gemm,  cudaFuncAttributeMaxDynamicSharedMemorySize, P3_SMEM);
    cudaFuncSetAttribute(attn_hmma, cudaFuncAttributeMaxDynamicSharedMemorySize, SMEM_ATT);

    const int setup_blocks = (WPREN + WON + 255) / 256;   // 576
    setup_k<<<setup_blocks, 256>>>(Wf, Wg, Wh, Wo);
    pre_gemm<<<ROWS/64*2, 256, P1_SMEM>>>(x, bf, bg, bh);
    attn_hmma<<<512, 256, SMEM_ATT>>>();
    out_gemm<<<ROWS/64*2, 256, P3_SMEM>>>(bo, gamma, x, out);
}